// round 17
// baseline (speedup 1.0000x reference)
#include <cuda_runtime.h>
#include <cuda_fp16.h>
#include <cstdint>

// Conv2d 3x3 s1 p1: x[32,64,56,56] * w[128,64,3,3] -> out[32,128,56,56]
// FP16 implicit GEMM (fp32 accum), mma.sync m16n8k16.
// CTA = 128oc x 64px, 4 warps of 64x32, 3 CTAs/SM (12 warps/SM).
// B halo gathered DIRECTLY from fp32 NCHW x (predicated LDG + cvt + STS.64,
// channel-permuted, conflict-free). A taps cp.async double-buffered.
// Only remaining prep kernel: weight reorder (k_wt).

#define B_    32
#define CIN   64
#define COUT  128
#define HW    56
#define PADW  58
#define IMG   (HW*HW)             // 3136
#define NPIX  (B_*IMG)            // 100352
#define NT    64                  // pixels per CTA (64 | 3136: no batch crossing)
#define NCTA  (NPIX/NT)           // 1568
#define BSTRB 160                 // bytes per halo slot row (128B data + pad)
#define NSLOT 192                 // staged halo slot rows (max read slot = 181)
#define NTHR  128
#define PTHR  256                 // prep threads
#define CELLS_PER_B (PADW*PADW)   // 3364

__device__ __half g_wt2[9*COUT*CIN];                 // fragment-major fp16 weights

static __device__ __forceinline__ void mma16(float* d, const uint32_t* a,
                                             uint32_t b0, uint32_t b1) {
    asm volatile("mma.sync.aligned.m16n8k16.row.col.f32.f16.f16.f32 "
                 "{%0,%1,%2,%3}, {%4,%5,%6,%7}, {%8,%9}, {%0,%1,%2,%3};"
                 : "+f"(d[0]), "+f"(d[1]), "+f"(d[2]), "+f"(d[3])
                 : "r"(a[0]), "r"(a[1]), "r"(a[2]), "r"(a[3]), "r"(b0), "r"(b1));
}
static __device__ __forceinline__ void cp16(uint32_t saddr, const void* g) {
    asm volatile("cp.async.cg.shared.global [%0], [%1], 16;" :: "r"(saddr), "l"(g));
}
#define CP_COMMIT() asm volatile("cp.async.commit_group;" ::: "memory")
#define CP_WAIT(n)  asm volatile("cp.async.wait_group %0;" :: "n"(n) : "memory")

// ---------------- weight prep kernel ----------------
// per kidx: [s(4)][atom(8)][lane(32)][j(8 halves)] = 8192 halves
__global__ void k_wt(const float* __restrict__ w) {
    int i = blockIdx.x * PTHR + threadIdx.x;
    if (i >= 9 * COUT * CIN) return;
    int kidx = i / 8192;
    int e    = i % 8192;
    int s    = e / 2048;
    int atom = (e / 256) & 7;
    int lane = (e >> 3) & 31;
    int j    = e & 7;
    int oc = atom * 16 + (lane >> 2) + ((j >> 1) & 1) * 8;
    int c  = s * 16 + 2 * (lane & 3) + (j & 1) + ((j >> 2) & 1) * 8;
    g_wt2[i] = __float2half_rn(w[((size_t)oc * CIN + c) * 9 + kidx]);
}

// ---------------- main kernel ----------------
// smem/CTA: [0] s_out4(16 u32)  [1024] A0,A1 (16384 B each)
//           [33792] halo (192 slots x 160 B = 30720)   total 64512
//   -> 3 CTAs/SM. Epilogue reuses [1024..] as sO[128][68] f32 (34816 B).
#define SM_A0   1024
#define SM_HALO (SM_A0 + 2*16384)
#define SM_TOT  (SM_HALO + NSLOT*BSTRB)

__global__ __launch_bounds__(NTHR, 3) void conv_mma(const float* __restrict__ x,
                                                    float* __restrict__ out) {
    extern __shared__ char smem[];
    uint32_t* s_out4 = (uint32_t*)smem;
    const uint32_t sb = (uint32_t)__cvta_generic_to_shared(smem);

    const int t = threadIdx.x;
    const int w = t >> 5, lane = t & 31;
    const int g = lane >> 2, tig = lane & 3;
    const int ocHalf = w & 1, pxHalf = w >> 1;       // 2 x 2 warp grid, 64x32 tiles
    const int base = blockIdx.x * NT;

    // pad-cell index of the tile's first pixel's top-left tap
    int cell0;
    {
        int bb = base / IMG, rr = base - bb * IMG;
        int y = rr / HW, xx = rr - y * HW;
        cell0 = (bb * PADW + y) * PADW + xx;
    }

    // per-thread B slot byte-offsets for the 4 'an' sub-tiles
    uint32_t bOff[4];
    #pragma unroll
    for (int an = 0; an < 4; an++) {
        int pg = base + pxHalf * 32 + an * 8 + g;        // global pixel id
        int bb = pg / IMG, rr = pg - bb * IMG;
        int y = rr / HW, xx = rr - y * HW;
        int slot = (bb * PADW + y) * PADW + xx - cell0;  // 0..65
        bOff[an] = SM_HALO + (uint32_t)slot * BSTRB + tig * 8;
    }
    if (t < NT / 4) {
        int ng = base + t * 4;
        int bb = ng / IMG, rr = ng - bb * IMG;
        s_out4[t] = (uint32_t)bb * COUT * IMG + rr;
    }

    // stage A tap kidx into buffer buf (0/1)
    auto stageA = [&](int kidx, int buf) {
        const uint32_t abuf = sb + SM_A0 + buf * 16384;
        const __half* asrc = g_wt2 + kidx * 8192;
        #pragma unroll
        for (int it = 0; it < 8; it++) {
            int i = t + it * NTHR;                       // 1024 x 16B
            cp16(abuf + i * 16, asrc + i * 8);
        }
    };
    stageA(0, 0); CP_COMMIT();

    // ---- gather the 192-slot halo directly from fp32 NCHW x ----
    // task i = (slot sl, pos-group pg). pos-group holds channels
    // {u, u+1, u+8, u+9}, u = 16*(pg>>2) + 2*(pg&3)  (matches permuted layout).
    // STS.64: 16 lanes cover pg 0..15 of one slot -> even banks once each: CF.
    #pragma unroll
    for (int it = 0; it < 24; it++) {
        int i = t + it * NTHR;                           // 3072 tasks
        int sl = i >> 4, pg = i & 15;
        int cell = cell0 + sl;
        int bb2 = cell / CELLS_PER_B;
        int rc = cell - bb2 * CELLS_PER_B;
        int py = rc / PADW, pxx = rc - py * PADW;
        bool v = (py >= 1) && (py <= HW) && (pxx >= 1) && (pxx <= HW);
        int u = ((pg >> 2) << 4) + ((pg & 3) << 1);
        const float* xp = x + ((size_t)(bb2 * CIN + u) * IMG
                               + (py - 1) * HW + (pxx - 1));
        float f0 = v ? xp[0]       : 0.f;
        float f1 = v ? xp[IMG]     : 0.f;
        float f2 = v ? xp[8 * IMG] : 0.f;
        float f3 = v ? xp[9 * IMG] : 0.f;
        __half2 lo = __floats2half2_rn(f0, f1);
        __half2 hi = __floats2half2_rn(f2, f3);
        uint32_t rlo = *(uint32_t*)&lo, rhi = *(uint32_t*)&hi;
        uint32_t addr = sb + SM_HALO + sl * BSTRB + pg * 8;
        asm volatile("st.shared.v2.b32 [%0], {%1,%2};"
                     :: "r"(addr), "r"(rlo), "r"(rhi) : "memory");
    }

    float d[4][4][4];                                 // [ao][an][j] = 64 regs
    #pragma unroll
    for (int ao = 0; ao < 4; ao++)
        #pragma unroll
        for (int an = 0; an < 4; an++)
            #pragma unroll
            for (int j = 0; j < 4; j++) d[ao][an][j] = 0.f;

    #pragma unroll 3
    for (int kk = 0; kk < 9; kk++) {
        CP_WAIT(0);                    // A(kk) committed one full iter ago
        __syncthreads();               // all warps past compute(kk-1); halo visible
        if (kk < 8) { stageA(kk + 1, (kk + 1) & 1); CP_COMMIT(); }

        const char* sA = smem + SM_A0 + (kk & 1) * 16384;
        const char* aBase = sA + (ocHalf * 4) * 512 + lane * 16;
        const uint32_t tapB = (uint32_t)((kk / 3) * PADW + (kk % 3)) * BSTRB;

        #pragma unroll
        for (int s = 0; s < 4; s++) {
            uint32_t a[4][4];
            #pragma unroll
            for (int ao = 0; ao < 4; ao++) {
                uint4 v = *(const uint4*)(aBase + s * 4096 + ao * 512);
                a[ao][0] = v.x; a[ao][1] = v.y; a[ao][2] = v.z; a[ao][3] = v.w;
            }
            uint32_t b0[4], b1[4];
            #pragma unroll
            for (int an = 0; an < 4; an++) {
                uint2 v2 = *(const uint2*)(smem + bOff[an] + tapB + s * 32);
                b0[an] = v2.x; b1[an] = v2.y;
            }
            #pragma unroll
            for (int ao = 0; ao < 4; ao++)
                #pragma unroll
                for (int an = 0; an < 4; an++)
                    mma16(d[ao][an], a[ao], b0[an], b1[an]);
        }
    }

    // epilogue: accums -> sO[oc][68] -> coalesced STG.128
    __syncthreads();
    float* sO = (float*)(smem + SM_A0);
    #pragma unroll
    for (int ao = 0; ao < 4; ao++)
        #pragma unroll
        for (int an = 0; an < 4; an++)
            #pragma unroll
            for (int j = 0; j < 4; j++) {
                int oc = ocHalf * 64 + ao * 16 + g + ((j >> 1) << 3);
                int px = pxHalf * 32 + an * 8 + 2 * tig + (j & 1);
                sO[oc * 68 + px] = d[ao][an][j];
            }
    __syncthreads();

    #pragma unroll
    for (int it = 0; it < 16; it++) {
        int i = t + it * NTHR;                           // 2048 float4
        int oc = i >> 4, q = i & 15;
        float4 v = *(const float4*)(sO + oc * 68 + q * 4);
        *(float4*)(out + (size_t)s_out4[q] + (size_t)oc * IMG) = v;
    }
}

extern "C" void kernel_launch(void* const* d_in, const int* in_sizes, int n_in,
                              void* d_out, int out_size) {
    const float* x = (const float*)d_in[0];
    const float* w = (const float*)d_in[1];
    float* out = (float*)d_out;

    k_wt<<<(9 * COUT * CIN + PTHR - 1) / PTHR, PTHR>>>(w);

    cudaFuncSetAttribute(conv_mma, cudaFuncAttributeMaxDynamicSharedMemorySize, SM_TOT);
    conv_mma<<<NCTA, NTHR, SM_TOT>>>(x, out);
}